// round 17
// baseline (speedup 1.0000x reference)
#include <cuda_runtime.h>
#include <cuda_bf16.h>
#include <math.h>
#include <stdint.h>

// Problem constants
#define NN_MAX 50000
#define NE_MAX 400000
#define DIM 256
#define NHEAD 4

typedef __nv_bfloat16 bf16;

// ---------------- scratch (static __device__ arrays, no allocation) -------
__device__ bf16     g_node_projh[NN_MAX * 768];  // [q|k|v] per node
__device__ bf16     g_edge_projh[NE_MAX * 768];  // [q|k|v] per edge
__device__ bf16     g_att_bf[NN_MAX * DIM];      // attention output (feeds Wo)
__device__ float    g_tmp[NN_MAX * DIM];         // after Wo
__device__ float    g_h1[NN_MAX * DIM];          // after LN1 (fp32)
__device__ bf16     g_h1_bf[NN_MAX * DIM];       // after LN1 (bf16)
__device__ bf16     g_ff_bf[NN_MAX * 1024];      // after FFN1+gelu (bf16)
__device__ float    g_ff2[NN_MAX * DIM];         // after FFN2
// CSR attention scratch
__device__ int      g_cnt[NN_MAX];               // edges per src
__device__ int      g_fill[NN_MAX];              // fill cursors
__device__ int      g_off[NN_MAX + 1];           // exclusive offsets
__device__ bf16     g_wv[(size_t)NE_MAX * 256];  // ex * (vn+ve) per edge slot
__device__ float    g_ex[NE_MAX * 4];            // ex per (slot, head)
// transposed weights [N][K] K-major, bf16 (built per launch)
__device__ bf16     g_wt_n[768 * 256];
__device__ bf16     g_wt_e[768 * 256];
__device__ bf16     g_wt_wo[256 * 256];
__device__ bf16     g_wt_f1[1024 * 256];
__device__ bf16     g_wt_f2[256 * 1024];
__device__ float    g_bias_n[768];

// ---------------- helpers --------------------------------------------------
__device__ __forceinline__ float gelu_exact(float x) {
    return 0.5f * x * (1.0f + erff(x * 0.70710678118654752440f));
}
__device__ __forceinline__ unsigned pack_bf16x2(float x, float y) {
    __nv_bfloat162 h = __float22bfloat162_rn(make_float2(x, y));
    return reinterpret_cast<unsigned&>(h);
}
__device__ __forceinline__ void mma_bf16(float* c, const unsigned* a,
                                         const unsigned* b) {
    asm volatile(
        "mma.sync.aligned.m16n8k16.row.col.f32.bf16.bf16.f32 "
        "{%0,%1,%2,%3}, {%4,%5,%6,%7}, {%8,%9}, {%0,%1,%2,%3};"
        : "+f"(c[0]), "+f"(c[1]), "+f"(c[2]), "+f"(c[3])
        : "r"(a[0]), "r"(a[1]), "r"(a[2]), "r"(a[3]),
          "r"(b[0]), "r"(b[1]));
}
__device__ __forceinline__ void ldm_x4(unsigned* r, unsigned addr) {
    asm volatile("ldmatrix.sync.aligned.m8n8.x4.shared.b16 {%0,%1,%2,%3}, [%4];"
                 : "=r"(r[0]), "=r"(r[1]), "=r"(r[2]), "=r"(r[3]) : "r"(addr));
}
__device__ __forceinline__ void cpa16(unsigned s, const void* g) {
    asm volatile("cp.async.ca.shared.global [%0], [%1], 16;"
                 :: "r"(s), "l"(g));
}
__device__ __forceinline__ void cpa_commit() {
    asm volatile("cp.async.commit_group;");
}
template <int N>
__device__ __forceinline__ void cpa_wait() {
    asm volatile("cp.async.wait_group %0;" :: "n"(N));
}

// ---------------- fused prologue kernels -----------------------------------
__device__ __forceinline__ void transpose_tile(
    const float* __restrict__ W, int ldw, int row_off,
    bf16* __restrict__ Wt, int K, int n_off, int tn, int tk) {
    __shared__ float tile[32][33];
    int n0 = tn * 32, k0 = tk * 32;
    int tx = threadIdx.x, ty = threadIdx.y;  // 32 x 8
#pragma unroll
    for (int i = ty; i < 32; i += 8)
        tile[i][tx] = W[(size_t)(row_off + k0 + i) * ldw + n0 + tx];
    __syncthreads();
#pragma unroll
    for (int i = ty; i < 32; i += 8)
        Wt[(size_t)(n_off + n0 + i) * K + k0 + tx] = __float2bfloat16(tile[tx][i]);
}

__global__ void k_prep_node(const float* __restrict__ Wq_w,
                            const float* __restrict__ Wq_b,
                            const float* __restrict__ Wkv_w,
                            const float* __restrict__ Wkv_b,
                            const float* __restrict__ Wo_w,
                            const float* __restrict__ f1w,
                            const float* __restrict__ f2w) {
    int id = blockIdx.x;
    if (id < 64) {
        transpose_tile(Wq_w, 256, 0, g_wt_n, 256, 0, id & 7, id >> 3);
    } else if (id < 192) {
        int j = id - 64;
        transpose_tile(Wkv_w, 512, 0, g_wt_n, 256, 256, j % 16, j / 16);
    } else if (id < 256) {
        int j = id - 192;
        transpose_tile(Wo_w, 256, 0, g_wt_wo, 256, 0, j & 7, j >> 3);
    } else if (id < 512) {
        int j = id - 256;
        transpose_tile(f1w, 1024, 0, g_wt_f1, 256, 0, j % 32, j / 32);
    } else if (id < 768) {
        int j = id - 512;
        transpose_tile(f2w, 256, 0, g_wt_f2, 1024, 0, j % 8, j / 8);
    } else {
        int i = (id - 768) * 256 + threadIdx.y * 32 + threadIdx.x;
        if (i < 256) g_bias_n[i] = Wq_b[i];
        else if (i < 768) g_bias_n[i] = Wkv_b[i - 256];
    }
}

__global__ void k_prep_edge(const float* __restrict__ Wq_w,
                            const float* __restrict__ Wkv_w) {
    int id = blockIdx.x;
    if (id < 64) {
        transpose_tile(Wq_w, 256, 256, g_wt_e, 256, 0, id & 7, id >> 3);
    } else {
        int j = id - 64;
        transpose_tile(Wkv_w, 512, 256, g_wt_e, 256, 256, j % 16, j / 16);
    }
}

// ---------------- CSR build (stream 3, overlaps GEMMs) ---------------------
__global__ void k_zero_cnt(int NN) {
    int i = blockIdx.x * blockDim.x + threadIdx.x;
    if (i < NN) { g_cnt[i] = 0; g_fill[i] = 0; }
}
__global__ void k_count(const int* __restrict__ ei, int NE) {
    int i = blockIdx.x * blockDim.x + threadIdx.x;
    if (i < NE) atomicAdd(&g_cnt[ei[i]], 1);
}
// one-block exclusive scan over g_cnt -> g_off (g_off[NN] = total)
__global__ __launch_bounds__(1024) void k_scan(int NN) {
    __shared__ int part[1024];
    int t = threadIdx.x;
    int chunk = (NN + 1023) / 1024;
    int beg = t * chunk;
    int end = beg + chunk; if (end > NN) end = NN;
    int s = 0;
    for (int i = beg; i < end && i < NN; i++) s += g_cnt[i];
    part[t] = s;
    __syncthreads();
    for (int off = 1; off < 1024; off <<= 1) {
        int v = (t >= off) ? part[t - off] : 0;
        __syncthreads();
        part[t] += v;
        __syncthreads();
    }
    int run = part[t] - s;   // exclusive prefix of this chunk
    for (int i = beg; i < end && i < NN; i++) {
        g_off[i] = run;
        run += g_cnt[i];
    }
    if (t == 1023) g_off[NN] = part[1023];
}

// ---------------- GEMM tiling constants ------------------------------------
#define RS 80                        // bytes per smem row (64 data + 16 pad)
#define MSTG (128 * RS)              // one matrix stage: 10240 B
#define PSTG (2 * MSTG)              // A+B stage pair: 20480 B
#define NSTAGE 4
#define GSM_BYTES (NSTAGE * PSTG)    // 81920 B (bf16-A kernel)
#define GSM_F32A (2 * MSTG + 4 * MSTG)  // 61440 B (fp32-A kernel)

// ---------------- GEMM epilogue (shared by both kernels) -------------------
__device__ __forceinline__ void gemm_epilogue(
    float acc[4][4][4], int rb, int cb, int M, int N,
    const float* bias, int act, int obf16, void* C,
    int wm, int wn, int g, int tg) {
#pragma unroll
    for (int mt = 0; mt < 4; mt++) {
        int r0 = rb + wm * 64 + mt * 16 + g;
#pragma unroll
        for (int nt = 0; nt < 4; nt++) {
            int lcol = wn * 32 + nt * 8 + tg * 2;
            int ccol = cb + lcol;
            float v0 = acc[mt][nt][0], v1 = acc[mt][nt][1];
            float v2 = acc[mt][nt][2], v3 = acc[mt][nt][3];
            if (bias) {
                float bb0 = bias[lcol], bb1 = bias[lcol + 1];
                v0 += bb0; v1 += bb1; v2 += bb0; v3 += bb1;
            }
            if (act == 1) {
                v0 = gelu_exact(v0); v1 = gelu_exact(v1);
                v2 = gelu_exact(v2); v3 = gelu_exact(v3);
            }
            if (obf16) {
                bf16* Cb = (bf16*)C;
                if (r0 < M)
                    *(unsigned*)(Cb + (size_t)r0 * N + ccol) = pack_bf16x2(v0, v1);
                if (r0 + 8 < M)
                    *(unsigned*)(Cb + (size_t)(r0 + 8) * N + ccol) = pack_bf16x2(v2, v3);
            } else {
                float* Cf = (float*)C;
                if (r0 < M) {
                    Cf[(size_t)r0 * N + ccol]     = v0;
                    Cf[(size_t)r0 * N + ccol + 1] = v1;
                }
                if (r0 + 8 < M) {
                    Cf[(size_t)(r0 + 8) * N + ccol]     = v2;
                    Cf[(size_t)(r0 + 8) * N + ccol + 1] = v3;
                }
            }
        }
    }
}

// ---------------- bf16-A GEMM (4-stage cp.async + ldmatrix) ----------------
__global__ __launch_bounds__(256)
void tgemm_bf(const bf16* __restrict__ A, int M, int K,
              const bf16* __restrict__ Wt, const float* __restrict__ bias,
              void* __restrict__ C, int N, int act, int obf16) {
    extern __shared__ char dsm[];
    const unsigned base = (unsigned)__cvta_generic_to_shared(dsm);

    const int cb = blockIdx.x * 128;
    const int rb = blockIdx.y * 128;

    const int t    = threadIdx.x;
    const int lane = t & 31;
    const int wid  = t >> 5;
    const int wm   = wid & 1;
    const int wn   = wid >> 1;
    const int g    = lane >> 2;
    const int tg   = lane & 3;

    float acc[4][4][4];
#pragma unroll
    for (int mt = 0; mt < 4; mt++)
#pragma unroll
        for (int nt = 0; nt < 4; nt++)
#pragma unroll
            for (int r = 0; r < 4; r++) acc[mt][nt][r] = 0.0f;

    const int NT = K / 32;
    const int s_row = t >> 1;
    const int s_c   = (t & 1) * 2;

    auto stage = [&](int kt) {
        unsigned sb = base + (kt & (NSTAGE - 1)) * PSTG;
        int k0 = kt * 32;
        int ga = rb + s_row; if (ga >= M) ga = M - 1;
#pragma unroll
        for (int cc = 0; cc < 2; cc++) {
            int c = s_c + cc;
            cpa16(sb + s_row * RS + c * 16, A + (size_t)ga * K + k0 + c * 8);
            cpa16(sb + MSTG + s_row * RS + c * 16,
                  Wt + (size_t)(cb + s_row) * K + k0 + c * 8);
        }
        cpa_commit();
    };

    stage(0);
    if (NT > 1) stage(1); else cpa_commit();
    if (NT > 2) stage(2); else cpa_commit();

    const unsigned aOff = (lane & 15) * RS + (lane >> 4) * 16;
    const unsigned bOff4 = (lane & 7) * RS + ((lane >> 3) & 1) * 16
                         + (lane >> 4) * 8 * RS;

    for (int kt = 0; kt < NT; kt++) {
        cpa_wait<2>();
        __syncthreads();
        if (kt + 3 < NT) stage(kt + 3); else cpa_commit();

        const unsigned aB = base + (kt & (NSTAGE - 1)) * PSTG;
        const unsigned bB = aB + MSTG;
#pragma unroll
        for (int ko = 0; ko < 2; ko++) {
            unsigned a[4][4], b[4][2];
#pragma unroll
            for (int mt = 0; mt < 4; mt++)
                ldm_x4(a[mt], aB + (wm * 64 + mt * 16) * RS + aOff + ko * 32);
#pragma unroll
            for (int p = 0; p < 2; p++) {
                unsigned r4[4];
                ldm_x4(r4, bB + (wn * 32 + p * 16) * RS + bOff4 + ko * 32);
                b[2 * p][0] = r4[0]; b[2 * p][1] = r4[1];
                b[2 * p + 1][0] = r4[2]; b[2 * p + 1][1] = r4[3];
            }
#pragma unroll
            for (int mt = 0; mt < 4; mt++)
#pragma unroll
                for (int nt = 0; nt < 4; nt++)
                    mma_bf16(acc[mt][nt], a[mt], b[nt]);
        }
    }

    gemm_epilogue(acc, rb, cb, M, N, bias, act, obf16, C, wm, wn, g, tg);
}

// ---------------- fp32-A GEMM: A converted in-kernel (no cvt pass) ---------
// A fp32 staged via LDG.128 one chunk ahead -> bf16 STS into 2-buffer region.
// B keeps the 4-stage cp.async pipeline. smem: [Abf x2][B x4] = 61440 B.
__global__ __launch_bounds__(256)
void tgemm_f32a(const float* __restrict__ A, int M, int K,
                const bf16* __restrict__ Wt, const float* __restrict__ bias,
                void* __restrict__ C, int N, int act, int obf16) {
    extern __shared__ char dsm[];
    const unsigned base = (unsigned)__cvta_generic_to_shared(dsm);
    const unsigned bbase = base + 2 * MSTG;

    const int cb = blockIdx.x * 128;
    const int rb = blockIdx.y * 128;

    const int t    = threadIdx.x;
    const int lane = t & 31;
    const int wid  = t >> 5;
    const int wm   = wid & 1;
    const int wn   = wid >> 1;
    const int g    = lane >> 2;
    const int tg   = lane & 3;

    float acc[4][4][4];
#pragma unroll
    for (int mt = 0; mt < 4; mt++)
#pragma unroll
        for (int nt = 0; nt < 4; nt++)
#pragma unroll
            for (int r = 0; r < 4; r++) acc[mt][nt][r] = 0.0f;

    const int NT = K / 32;
    const int s_row = t >> 1;          // 0..127
    const int s_half = t & 1;          // half of the 32-float chunk row

    int ga = rb + s_row; if (ga >= M) ga = M - 1;
    const float* arow = A + (size_t)ga * K + s_half * 16;

    float4 ar[4];
    auto ldgA = [&](int kt) {
        const float* p = arow + kt * 32;
        ar[0] = *(const float4*)(p);
        ar[1] = *(const float4*)(p + 4);
        ar[2] = *(const float4*)(p + 8);
        ar[3] = *(const float4*)(p + 12);
    };
    auto stsA = [&](int kt) {
        uint4 w0, w1;
        w0.x = pack_bf16x2(ar[0].x, ar[0].y);
        w0.y = pack_bf16x2(ar[0].z, ar[0].w);
        w0.z = pack_bf16x2(ar[1].x, ar[1].y);
        w0.w = pack_bf16x2(ar[1].z, ar[1].w);
        w1.x = pack_bf16x2(ar[2].x, ar[2].y);
        w1.y = pack_bf16x2(ar[2].z, ar[2].w);
        w1.z = pack_bf16x2(ar[3].x, ar[3].y);
        w1.w = pack_bf16x2(ar[3].z, ar[3].w);
        char* p = dsm + (kt & 1) * MSTG + s_row * RS + s_half * 32;
        *(uint4*)p = w0;
        *(uint4*)(p + 16) = w1;
    };
    auto stageB = [&](int kt) {
        unsigned sb = bbase + (kt & 3) * MSTG;
        int k0 = kt * 32;
#pragma unroll
        for (int cc = 0; cc < 2; cc++) {
            int c = s_half * 2 + cc;
            cpa16(sb + s_row * RS + c * 16,
                  Wt + (size_t)(cb + s_row) * K + k0 + c * 8);
        }
        cpa_commit();
    };

    // prologue
    ldgA(0); stsA(0);
    if (NT > 1) ldgA(1);           // regs hold stage 1
    stageB(0);
    if (NT > 1) stageB(1); else cpa_commit();
    if (NT > 2) stageB(2); else cpa_commit();

    const unsigned aOff = (lane & 15) * RS + (lane >> 4) * 16;
    const unsigned bOff4 = (lane & 7) * RS + ((lane >> 3) & 1) * 16
                         + (lane >> 4) * 8 * RS;

    for (int kt = 0; kt < NT; kt++) {
        cpa_wait<2>();
        __syncthreads();    // B kt visible; A STS (kt) visible; chunk kt-1 reads done
        if (kt + 3 < NT) stageB(kt + 3); else cpa_commit();
        if (kt + 1 < NT) stsA(kt + 1);     // write other A buffer
        if (kt + 2 < NT) ldgA(kt + 2);     // prefetch next-next A

        const unsigned aB = base + (kt & 1) * MSTG;
        const unsigned bB = bbase + (kt & 3) * MSTG;
#pragma unroll
        for (int ko = 0; ko < 2; ko++) {
            unsigned a[4][4], b[4][2];
#pragma unroll
            for (int mt = 0; mt < 4; mt++)
                ldm_x4(a[mt], aB + (wm * 64 + mt * 16) * RS + aOff + ko * 32);
#pragma unroll
            for (int p = 0; p < 2; p++) {
                unsigned r4[4];
                ldm_x4(r4, bB + (wn * 32 + p * 16) * RS + bOff4 + ko * 32);
                b[2 * p][0] = r4[0]; b[2 * p][1] = r4[1];
                b[2 * p + 1][0] = r4[2]; b[2 * p + 1][1] = r4[3];
            }
#pragma unroll
            for (int mt = 0; mt < 4; mt++)
#pragma unroll
                for (int nt = 0; nt < 4; nt++)
                    mma_bf16(acc[mt][nt], a[mt], b[nt]);
        }
    }

    gemm_epilogue(acc, rb, cb, M, N, bias, act, obf16, C, wm, wn, g, tg);
}

// ------- edge pass: score + exp + CSR slot claim + streamed wv write ------
__global__ void k_edge_attn(const int* __restrict__ ei, int NE) {
    int w = (blockIdx.x * blockDim.x + threadIdx.x) >> 5;
    int lane = threadIdx.x & 31;
    if (w >= NE) return;
    int src = ei[w];
    int dst = ei[NE + w];
    const bf16* qn = g_node_projh + (size_t)src * 768;
    const bf16* kn = g_node_projh + (size_t)dst * 768 + 256;
    const bf16* vn = g_node_projh + (size_t)dst * 768 + 512;
    const bf16* qe = g_edge_projh + (size_t)w * 768;
    const bf16* ke = qe + 256;
    const bf16* ve = qe + 512;

    uint4 a = *(const uint4*)(qn + lane * 8);
    uint4 b = *(const uint4*)(qe + lane * 8);
    uint4 c = *(const uint4*)(kn + lane * 8);
    uint4 d = *(const uint4*)(ke + lane * 8);

    float s = 0.f;
    {
        const __nv_bfloat162* q1 = (const __nv_bfloat162*)&a;
        const __nv_bfloat162* q2 = (const __nv_bfloat162*)&b;
        const __nv_bfloat162* k1 = (const __nv_bfloat162*)&c;
        const __nv_bfloat162* k2 = (const __nv_bfloat162*)&d;
#pragma unroll
        for (int j = 0; j < 4; j++) {
            float2 x1 = __bfloat1622float2(q1[j]);
            float2 x2 = __bfloat1622float2(q2[j]);
            float2 y1 = __bfloat1622float2(k1[j]);
            float2 y2 = __bfloat1622float2(k2[j]);
            s += (x1.x + x2.x) * (y1.x + y2.x) + (x1.y + x2.y) * (y1.y + y2.y);
        }
    }
#pragma unroll
    for (int off = 1; off < 8; off <<= 1)
        s += __shfl_xor_sync(0xffffffffu, s, off);

    float ex = expf(s * 0.125f);   // 1/sqrt(64); scores O(1), no max needed
    int h = lane >> 3;

    int slot;
    if (lane == 0) slot = g_off[src] + atomicAdd(&g_fill[src], 1);
    slot = __shfl_sync(0xffffffffu, slot, 0);

    if ((lane & 7) == 0) g_ex[slot * 4 + h] = ex;

    uint4 va = *(const uint4*)(vn + lane * 8);
    uint4 vb = *(const uint4*)(ve + lane * 8);
    const __nv_bfloat162* v1 = (const __nv_bfloat162*)&va;
    const __nv_bfloat162* v2 = (const __nv_bfloat162*)&vb;
    uint4 outw;
    __nv_bfloat162* ow = (__nv_bfloat162*)&outw;
#pragma unroll
    for (int j = 0; j < 4; j++) {
        float2 x1 = __bfloat1622float2(v1[j]);
        float2 x2 = __bfloat1622float2(v2[j]);
        ow[j] = __float22bfloat162_rn(
            make_float2(ex * (x1.x + x2.x), ex * (x1.y + x2.y)));
    }
    *(uint4*)(g_wv + (size_t)slot * 256 + lane * 8) = outw;
}

// ------- node gather: fp32 accumulate over CSR range, normalize, write ----
__global__ void k_gather(int NN) {
    int node = (blockIdx.x * blockDim.x + threadIdx.x) >> 5;
    int lane = threadIdx.x & 31;
    if (node >= NN) return;
    int beg = g_off[node];
    int end = g_off[node + 1];
    int h = lane >> 3;
    float acc[8] = {0.f, 0.f, 0.f, 0.f, 0.f, 0.f, 0.f, 0.f};
    float den = 0.f;
    for (int sIdx = beg; sIdx < end; sIdx++) {
        den += g_ex[sIdx * 4 + h];
        uint4 wv = *(const uint4*)(g_wv + (size_t)sIdx * 256 + lane * 8);
        const __nv_bfloat162* ww = (const __nv_bfloat162*)&wv;
#pragma unroll
        for (int j = 0; j < 4; j++) {
            float2 v = __bfloat1622float2(ww[j]);
            acc[2 * j]     += v.x;
            acc[2 * j + 1] += v.y;
        }
    }
    float inv = (den > 0.f) ? (1.f / den) : 0.f;
    uint4 outw;
    unsigned* ow = (unsigned*)&outw;
#pragma unroll
    for (int j = 0; j < 4; j++)
        ow[j] = pack_bf16x2(acc[2 * j] * inv, acc[2 * j + 1] * inv);
    *(uint4*)(g_att_bf + (size_t)node * 256 + lane * 8) = outw;
}

// ------------- layernorm (warp per row of 256), optional bf16 copy --------
__global__ void k_ln(const float* __restrict__ x, const float* __restrict__ res,
                     const float* __restrict__ g, const float* __restrict__ b,
                     float* __restrict__ out, bf16* __restrict__ out_bf, int M) {
    int w = (blockIdx.x * blockDim.x + threadIdx.x) >> 5;
    int lane = threadIdx.x & 31;
    if (w >= M) return;
    float v[8];
    float s = 0.f;
#pragma unroll
    for (int j = 0; j < 8; j++) {
        int i = lane + 32 * j;
        v[j] = x[(size_t)w * 256 + i] + res[(size_t)w * 256 + i];
        s += v[j];
    }
#pragma unroll
    for (int off = 16; off; off >>= 1) s += __shfl_xor_sync(0xffffffffu, s, off);
    float mu = s * (1.0f / 256.0f);
    float q = 0.f;
#pragma unroll
    for (int j = 0; j < 8; j++) { float d = v[j] - mu; q += d * d; }
#pragma unroll
    for (int off = 16; off; off >>= 1) q += __shfl_xor_sync(0xffffffffu, q, off);
    float rstd = rsqrtf(q * (1.0f / 256.0f) + 1e-5f);
#pragma unroll
    for (int j = 0; j < 8; j++) {
        int i = lane + 32 * j;
        float y = (v[j] - mu) * rstd * g[i] + b[i];
        out[(size_t)w * 256 + i] = y;
        if (out_bf) out_bf[(size_t)w * 256 + i] = __float2bfloat16(y);
    }
}

// ---------------- host launch ----------------------------------------------
extern "C" void kernel_launch(void* const* d_in, const int* in_sizes, int n_in,
                              void* d_out, int out_size) {
    const float* h_n   = (const float*)d_in[0];
    const float* h_e   = (const float*)d_in[1];
    const int*   ei    = (const int*)d_in[2];   // int32 (JAX x64 disabled)
    const float* Wq_w  = (const float*)d_in[3];
    const float* Wq_b  = (const float*)d_in[4];
    const float* Wkv_w = (const float*)d_in[5];
    const float* Wkv_b = (const float*)d_in[6];
    const float* Wo_w  = (const float*)d_in[7];
    const float* Wo_b  = (const float*)d_in[8];
    const float* ln1_g = (const float*)d_in[9];
    const float* ln1_b = (const float*)d_in[10];
    const float* f1w   = (const float*)d_in[11];
    const float* f1b   = (const float*)d_in[12];
    const float* f2w   = (const float*)d_in[13];
    const float* f2b   = (const float*)d_in[14];
    const float* ln2_g = (const float*)d_in[15];
    const float* ln2_b = (const float*)d_in[16];
    float* out = (float*)d_out;

    int NN = in_sizes[0] / DIM;
    int NE = in_sizes[1] / DIM;

    static int inited = 0;
    static cudaStream_t s2, s3;
    static cudaEvent_t evFork, evJoin2, evJoin3;
    if (!inited) {
        cudaFuncSetAttribute(tgemm_bf,
                             cudaFuncAttributeMaxDynamicSharedMemorySize,
                             GSM_BYTES);
        cudaFuncSetAttribute(tgemm_f32a,
                             cudaFuncAttributeMaxDynamicSharedMemorySize,
                             GSM_F32A);
        cudaStreamCreateWithFlags(&s2, cudaStreamNonBlocking);
        cudaStreamCreateWithFlags(&s3, cudaStreamNonBlocking);
        cudaEventCreateWithFlags(&evFork, cudaEventDisableTiming);
        cudaEventCreateWithFlags(&evJoin2, cudaEventDisableTiming);
        cudaEventCreateWithFlags(&evJoin3, cudaEventDisableTiming);
        inited = 1;
    }

    void *p_nph, *p_eph, *p_attb, *p_tmp;
    void *p_h1, *p_h1b, *p_ffb, *p_ff2;
    void *p_wtn, *p_wte, *p_wtwo, *p_wtf1, *p_wtf2, *p_bn;
    cudaGetSymbolAddress(&p_nph, g_node_projh);
    cudaGetSymbolAddress(&p_eph, g_edge_projh);
    cudaGetSymbolAddress(&p_attb, g_att_bf);
    cudaGetSymbolAddress(&p_tmp, g_tmp);
    cudaGetSymbolAddress(&p_h1, g_h1);
    cudaGetSymbolAddress(&p_h1b, g_h1_bf);
    cudaGetSymbolAddress(&p_ffb, g_ff_bf);
    cudaGetSymbolAddress(&p_ff2, g_ff2);
    cudaGetSymbolAddress(&p_wtn, g_wt_n);
    cudaGetSymbolAddress(&p_wte, g_wt_e);
    cudaGetSymbolAddress(&p_wtwo, g_wt_wo);
    cudaGetSymbolAddress(&p_wtf1, g_wt_f1);
    cudaGetSymbolAddress(&p_wtf2, g_wt_f2);
    cudaGetSymbolAddress(&p_bn, g_bias_n);

    dim3 tb(32, 8);

    // ---- fork ----
    cudaEventRecord(evFork, 0);
    cudaStreamWaitEvent(s2, evFork, 0);
    cudaStreamWaitEvent(s3, evFork, 0);

    // node branch (s2): weight prep, node projections (fp32 A direct)
    k_prep_node<<<771, tb, 0, s2>>>(Wq_w, Wq_b, Wkv_w, Wkv_b, Wo_w, f1w, f2w);
    tgemm_f32a<<<dim3(6, (NN + 127) / 128), 256, GSM_F32A, s2>>>(
        h_n, NN, 256, (const bf16*)p_wtn, (const float*)p_bn, p_nph, 768, 0, 1);
    cudaEventRecord(evJoin2, s2);

    // CSR branch (s3): zero counters, count, scan
    k_zero_cnt<<<(NN + 255) / 256, 256, 0, s3>>>(NN);
    k_count<<<(NE + 255) / 256, 256, 0, s3>>>(ei, NE);
    k_scan<<<1, 1024, 0, s3>>>(NN);
    cudaEventRecord(evJoin3, s3);

    // edge branch (stream 0, critical path): fp32 A direct (no cvt pass)
    k_prep_edge<<<192, tb>>>(Wq_w, Wkv_w);
    tgemm_f32a<<<dim3(6, (NE + 127) / 128), 256, GSM_F32A>>>(
        h_e, NE, 256, (const bf16*)p_wte, nullptr, p_eph, 768, 0, 1);

    // ---- join ----
    cudaStreamWaitEvent(0, evJoin2, 0);
    cudaStreamWaitEvent(0, evJoin3, 0);

    // 4. edge pass: scores + exp + CSR streamed wv (one atomic per edge)
    k_edge_attn<<<(NE + 7) / 8, 256>>>(ei, NE);

    // 5. node gather: fp32 accumulate + normalize -> att_bf
    k_gather<<<(NN + 7) / 8, 256>>>(NN);

    // 6. output projection Wo (fp32 out)
    tgemm_bf<<<dim3(2, (NN + 127) / 128), 256, GSM_BYTES>>>(
        (const bf16*)p_attb, NN, 256, (const bf16*)p_wtwo, Wo_b, p_tmp, 256, 0, 0);

    // 7. LN1(h_n + attn_proj) -> fp32 + bf16
    k_ln<<<(NN + 7) / 8, 256>>>(h_n, (const float*)p_tmp, ln1_g, ln1_b,
                                (float*)p_h1, (bf16*)p_h1b, NN);

    // 8. FFN1 + exact GELU -> bf16
    tgemm_bf<<<dim3(8, (NN + 127) / 128), 256, GSM_BYTES>>>(
        (const bf16*)p_h1b, NN, 256, (const bf16*)p_wtf1, f1b, p_ffb, 1024, 1, 1);

    // 9. FFN2 (fp32 out, K=1024)
    tgemm_bf<<<dim3(2, (NN + 127) / 128), 256, GSM_BYTES>>>(
        (const bf16*)p_ffb, NN, 1024, (const bf16*)p_wtf2, f2b, p_ff2, 256, 0, 0);

    // 10. LN2(h1 + ff) -> output
    k_ln<<<(NN + 7) / 8, 256>>>((const float*)p_h1, (const float*)p_ff2,
                                ln2_g, ln2_b, out, nullptr, NN);
}